// round 11
// baseline (speedup 1.0000x reference)
#include <cuda_runtime.h>
#include <cstdint>

// Segment offsets scratch: offsets[n] = first edge index whose segment id >= n.
#define MAX_SEGMENTS 131072
__device__ int g_offsets[MAX_SEGMENTS + 1];

#define BLOCK_THREADS 64   // 2 warps/CTA: minimal CTA-retirement max-of-k imbalance
#define EDGES_PER_THREAD 4

// ---------------------------------------------------------------------------
// Kernel 1: streaming offsets builder (index is SORTED): for each adjacent
// pair, boundaries n in (index[e-1], index[e]] get offsets[n] = e. Each
// thread handles 4 consecutive edges; in the int32 case the 4 values load as
// ONE uint4 (quarter the LDG count). Last edge fills the tail to N.
// Dtype robustness: JAX x64-off silently downcasts int64->int32; if truly
// int64 (values < 2^31) the low word sits at position 2m. Detect via 3
// trailing odd words (all zero iff int64 high halves).
// ---------------------------------------------------------------------------
__global__ void build_offsets_kernel(const unsigned int* __restrict__ w,
                                     int E, int N) {
    int t = blockIdx.x * blockDim.x + threadIdx.x;
    int e0 = t * EDGES_PER_THREAD;
    if (e0 >= E) return;

    int j = E - 1;
    if ((j & 1) == 0) j -= 1;
    unsigned int acc = 0;
    for (int k = 0; k < 3 && j - 2 * k >= 1; ++k)
        acc |= __ldg(&w[j - 2 * k]);
    const int shift = (acc == 0) ? 1 : 0;    // word index = m << shift

    int vals[EDGES_PER_THREAD];
    int nval = (E - e0 < EDGES_PER_THREAD) ? (E - e0) : EDGES_PER_THREAD;

    if (shift == 0 && nval == 4 && ((e0 & 3) == 0)) {
        uint4 v4 = __ldg(reinterpret_cast<const uint4*>(w) + (e0 >> 2));
        vals[0] = (int)v4.x; vals[1] = (int)v4.y;
        vals[2] = (int)v4.z; vals[3] = (int)v4.w;
    } else {
        #pragma unroll
        for (int k = 0; k < EDGES_PER_THREAD; ++k)
            if (k < nval)
                vals[k] = (int)__ldg(&w[((unsigned)(e0 + k)) << shift]);
    }

    int prev = (e0 == 0) ? -1 : (int)__ldg(&w[((unsigned)(e0 - 1)) << shift]);

    #pragma unroll
    for (int k = 0; k < EDGES_PER_THREAD; ++k) {
        if (k >= nval) break;
        int e = e0 + k;
        int cur = vals[k];
        for (int n = prev + 1; n <= cur; ++n)
            g_offsets[n] = e;
        if (e == E - 1) {
            for (int n = cur + 1; n <= N; ++n)
                g_offsets[n] = E;
        }
        prev = cur;
    }
}

// ---------------------------------------------------------------------------
// Kernel 2: ONE WARP PER SEGMENT (the empirically best scheduling across
// R3..R10). Inner loop: ceil(cnt/4) PREDICATED batches of 4 rows — every
// batch front-batches its loads (MLP=4 even on remainder batches, unlike
// serialized 2/1 tails), with only 2 long-lived accumulators + 4 transient
// load regs (R7 showed 8 live accumulators -> 72 regs -> occupancy collapse;
// this keeps regs ~44-48). Block=64. Lane l owns float4 column 4l (D=128 ->
// one column per lane). __ldcs read-once x stream, __stcs write-once output.
// Empty segments write zeros (output poisoned 0xAA, must be overwritten).
// ---------------------------------------------------------------------------
__global__ void __launch_bounds__(BLOCK_THREADS)
segment_mean_kernel(const float* __restrict__ x,
                    float* __restrict__ out,
                    int D, int N) {
    int gwarp = (blockIdx.x * blockDim.x + threadIdx.x) >> 5;
    int lane  = threadIdx.x & 31;
    if (gwarp >= N) return;

    int s = __ldg(&g_offsets[gwarp]);
    int e = __ldg(&g_offsets[gwarp + 1]);
    int cnt = e - s;
    float inv = (cnt > 0) ? (1.0f / (float)cnt) : 0.0f;

    for (int c = lane * 4; c < D; c += 32 * 4) {
        float4 a0 = make_float4(0.f, 0.f, 0.f, 0.f);
        float4 a1 = make_float4(0.f, 0.f, 0.f, 0.f);
        const float* p = x + (size_t)s * D + c;

        for (int r = s; r < e; r += 4, p += 4 * D) {
            int m = e - r;   // rows remaining in this batch (>=1)
            float4 v0, v1, v2, v3;
            bool b1 = (1 < m), b2 = (2 < m), b3 = (3 < m);
            v0 = __ldcs(reinterpret_cast<const float4*>(p));
            if (b1) v1 = __ldcs(reinterpret_cast<const float4*>(p + D));
            if (b2) v2 = __ldcs(reinterpret_cast<const float4*>(p + 2 * D));
            if (b3) v3 = __ldcs(reinterpret_cast<const float4*>(p + 3 * D));
            a0.x += v0.x; a0.y += v0.y; a0.z += v0.z; a0.w += v0.w;
            if (b1) { a1.x += v1.x; a1.y += v1.y; a1.z += v1.z; a1.w += v1.w; }
            if (b2) { a0.x += v2.x; a0.y += v2.y; a0.z += v2.z; a0.w += v2.w; }
            if (b3) { a1.x += v3.x; a1.y += v3.y; a1.z += v3.z; a1.w += v3.w; }
        }

        float4 res;
        res.x = (a0.x + a1.x) * inv;
        res.y = (a0.y + a1.y) * inv;
        res.z = (a0.z + a1.z) * inv;
        res.w = (a0.w + a1.w) * inv;
        __stcs(reinterpret_cast<float4*>(out + (size_t)gwarp * D + c), res);
    }
}

// ---------------------------------------------------------------------------
// Launch
// Inputs (metadata order): d_in[0] = x (float32, E*D), d_in[1] = index (E,
// int32 or int64 — detected on device), d_in[2] = dim_size (unused).
// ---------------------------------------------------------------------------
extern "C" void kernel_launch(void* const* d_in, const int* in_sizes, int n_in,
                              void* d_out, int out_size) {
    const float*        x   = (const float*)d_in[0];
    const unsigned int* idx = (const unsigned int*)d_in[1];
    float*              out = (float*)d_out;

    int E = in_sizes[1];          // 640000
    int D = in_sizes[0] / E;      // 128
    int N = out_size / D;         // 100000

    // Kernel 1: streaming segment boundaries, 4 edges per thread (uint4 path).
    {
        int threads = 256;
        long long work = ((long long)E + EDGES_PER_THREAD - 1) / EDGES_PER_THREAD;
        int blocks = (int)((work + threads - 1) / threads);
        build_offsets_kernel<<<blocks, threads>>>(idx, E, N);
    }

    // Kernel 2: one warp per segment, 2 warps per 64-thread block.
    {
        int warps_per_block = BLOCK_THREADS / 32;
        int blocks = (N + warps_per_block - 1) / warps_per_block;
        segment_mean_kernel<<<blocks, BLOCK_THREADS>>>(x, out, D, N);
    }
}

// round 12
// speedup vs baseline: 1.2318x; 1.2318x over previous
#include <cuda_runtime.h>
#include <cstdint>

// Segment offsets scratch: offsets[n] = first edge index whose segment id >= n.
#define MAX_SEGMENTS 131072
__device__ int g_offsets[MAX_SEGMENTS + 1];

#define BLOCK_THREADS 64   // 2 warps/CTA: minimal CTA-retirement max-of-k imbalance
#define EDGES_PER_THREAD 4

// ---------------------------------------------------------------------------
// Kernel 1: streaming offsets builder (index is SORTED): for each adjacent
// pair, boundaries n in (index[e-1], index[e]] get offsets[n] = e. Each
// thread handles 4 consecutive edges; in the int32 case the 4 values load as
// ONE uint4 (quarter the LDG count). Last edge fills the tail to N.
// Dtype robustness: JAX x64-off silently downcasts int64->int32; if truly
// int64 (values < 2^31) the low word sits at position 2m. Detect via 3
// trailing odd words (all zero iff int64 high halves).
// ---------------------------------------------------------------------------
__global__ void build_offsets_kernel(const unsigned int* __restrict__ w,
                                     int E, int N) {
    int t = blockIdx.x * blockDim.x + threadIdx.x;
    int e0 = t * EDGES_PER_THREAD;
    if (e0 >= E) return;

    int j = E - 1;
    if ((j & 1) == 0) j -= 1;
    unsigned int acc = 0;
    for (int k = 0; k < 3 && j - 2 * k >= 1; ++k)
        acc |= __ldg(&w[j - 2 * k]);
    const int shift = (acc == 0) ? 1 : 0;    // word index = m << shift

    int vals[EDGES_PER_THREAD];
    int nval = (E - e0 < EDGES_PER_THREAD) ? (E - e0) : EDGES_PER_THREAD;

    if (shift == 0 && nval == 4) {
        uint4 v4 = __ldg(reinterpret_cast<const uint4*>(w) + (e0 >> 2));
        vals[0] = (int)v4.x; vals[1] = (int)v4.y;
        vals[2] = (int)v4.z; vals[3] = (int)v4.w;
    } else {
        #pragma unroll
        for (int k = 0; k < EDGES_PER_THREAD; ++k)
            if (k < nval)
                vals[k] = (int)__ldg(&w[((unsigned)(e0 + k)) << shift]);
    }

    int prev = (e0 == 0) ? -1 : (int)__ldg(&w[((unsigned)(e0 - 1)) << shift]);

    #pragma unroll
    for (int k = 0; k < EDGES_PER_THREAD; ++k) {
        if (k >= nval) break;
        int e = e0 + k;
        int cur = vals[k];
        for (int n = prev + 1; n <= cur; ++n)
            g_offsets[n] = e;
        if (e == E - 1) {
            for (int n = cur + 1; n <= N; ++n)
                g_offsets[n] = E;
        }
        prev = cur;
    }
}

// ---------------------------------------------------------------------------
// Kernel 2: ONE WARP PER SEGMENT — the empirically best scheduling, in the
// EXACT R10 winning shape (59.1us main, regs 44, DRAM 76.4%): a cleanly
// unrolled x4 row loop with 4 transient load registers + 2 accumulators,
// then unroll-2 and scalar tails. (R11 proved manual predication serializes
// the loads via BSSY-guarded branches: 71us. R7 proved >2 live accumulators
// blow registers: 84us. Do not "improve" this loop shape again.)
// Block=64. Lane l owns float4 column 4l (D=128 -> one column per lane).
// __ldcs read-once x stream, __stcs write-once output. Empty segments write
// zeros (output poisoned 0xAA, must be overwritten).
// ---------------------------------------------------------------------------
__global__ void __launch_bounds__(BLOCK_THREADS)
segment_mean_kernel(const float* __restrict__ x,
                    float* __restrict__ out,
                    int D, int N) {
    int gwarp = (blockIdx.x * blockDim.x + threadIdx.x) >> 5;
    int lane  = threadIdx.x & 31;
    if (gwarp >= N) return;

    int s = __ldg(&g_offsets[gwarp]);
    int e = __ldg(&g_offsets[gwarp + 1]);
    int cnt = e - s;
    float inv = (cnt > 0) ? (1.0f / (float)cnt) : 0.0f;

    for (int c = lane * 4; c < D; c += 32 * 4) {
        float4 a0 = make_float4(0.f, 0.f, 0.f, 0.f);
        float4 a1 = make_float4(0.f, 0.f, 0.f, 0.f);
        const float* p = x + (size_t)s * D + c;
        int r = s;
        for (; r + 4 <= e; r += 4, p += 4 * D) {
            float4 v0 = __ldcs(reinterpret_cast<const float4*>(p));
            float4 v1 = __ldcs(reinterpret_cast<const float4*>(p + D));
            float4 v2 = __ldcs(reinterpret_cast<const float4*>(p + 2 * D));
            float4 v3 = __ldcs(reinterpret_cast<const float4*>(p + 3 * D));
            a0.x += v0.x; a0.y += v0.y; a0.z += v0.z; a0.w += v0.w;
            a1.x += v1.x; a1.y += v1.y; a1.z += v1.z; a1.w += v1.w;
            a0.x += v2.x; a0.y += v2.y; a0.z += v2.z; a0.w += v2.w;
            a1.x += v3.x; a1.y += v3.y; a1.z += v3.z; a1.w += v3.w;
        }
        if (r + 2 <= e) {
            float4 v0 = __ldcs(reinterpret_cast<const float4*>(p));
            float4 v1 = __ldcs(reinterpret_cast<const float4*>(p + D));
            a0.x += v0.x; a0.y += v0.y; a0.z += v0.z; a0.w += v0.w;
            a1.x += v1.x; a1.y += v1.y; a1.z += v1.z; a1.w += v1.w;
            r += 2; p += 2 * D;
        }
        if (r < e) {
            float4 v0 = __ldcs(reinterpret_cast<const float4*>(p));
            a0.x += v0.x; a0.y += v0.y; a0.z += v0.z; a0.w += v0.w;
        }
        float4 res;
        res.x = (a0.x + a1.x) * inv;
        res.y = (a0.y + a1.y) * inv;
        res.z = (a0.z + a1.z) * inv;
        res.w = (a0.w + a1.w) * inv;
        __stcs(reinterpret_cast<float4*>(out + (size_t)gwarp * D + c), res);
    }
}

// ---------------------------------------------------------------------------
// Launch
// Inputs (metadata order): d_in[0] = x (float32, E*D), d_in[1] = index (E,
// int32 or int64 — detected on device), d_in[2] = dim_size (unused).
// ---------------------------------------------------------------------------
extern "C" void kernel_launch(void* const* d_in, const int* in_sizes, int n_in,
                              void* d_out, int out_size) {
    const float*        x   = (const float*)d_in[0];
    const unsigned int* idx = (const unsigned int*)d_in[1];
    float*              out = (float*)d_out;

    int E = in_sizes[1];          // 640000
    int D = in_sizes[0] / E;      // 128
    int N = out_size / D;         // 100000

    // Kernel 1: streaming segment boundaries, 4 edges per thread (uint4 path).
    {
        int threads = 256;
        long long work = ((long long)E + EDGES_PER_THREAD - 1) / EDGES_PER_THREAD;
        int blocks = (int)((work + threads - 1) / threads);
        build_offsets_kernel<<<blocks, threads>>>(idx, E, N);
    }

    // Kernel 2: one warp per segment, 2 warps per 64-thread block.
    {
        int warps_per_block = BLOCK_THREADS / 32;
        int blocks = (N + warps_per_block - 1) / warps_per_block;
        segment_mean_kernel<<<blocks, BLOCK_THREADS>>>(x, out, D, N);
    }
}

// round 13
// speedup vs baseline: 1.3095x; 1.0630x over previous
#include <cuda_runtime.h>
#include <cstdint>

// Segment offsets scratch: offsets[n] = first edge index whose segment id >= n.
#define MAX_SEGMENTS 131072
__device__ int g_offsets[MAX_SEGMENTS + 1];

#define BLOCK_THREADS 64   // 2 warps/CTA: minimal CTA-retirement max-of-k imbalance
#define EDGES_PER_THREAD 4

// ---------------------------------------------------------------------------
// Kernel 1: streaming offsets builder (index is SORTED): for each adjacent
// pair, boundaries n in (index[e-1], index[e]] get offsets[n] = e. Each
// thread handles 4 consecutive edges; in the int32 case the 4 values load as
// ONE uint4 (quarter the LDG count). Last edge fills the tail to N.
// Dtype robustness: JAX x64-off silently downcasts int64->int32; if truly
// int64 (values < 2^31) the low word sits at position 2m. Detect via 3
// trailing odd words (all zero iff int64 high halves).
// ---------------------------------------------------------------------------
__global__ void build_offsets_kernel(const unsigned int* __restrict__ w,
                                     int E, int N) {
    int t = blockIdx.x * blockDim.x + threadIdx.x;
    int e0 = t * EDGES_PER_THREAD;
    if (e0 >= E) return;

    int j = E - 1;
    if ((j & 1) == 0) j -= 1;
    unsigned int acc = 0;
    for (int k = 0; k < 3 && j - 2 * k >= 1; ++k)
        acc |= __ldg(&w[j - 2 * k]);
    const int shift = (acc == 0) ? 1 : 0;    // word index = m << shift

    int vals[EDGES_PER_THREAD];
    int nval = (E - e0 < EDGES_PER_THREAD) ? (E - e0) : EDGES_PER_THREAD;

    if (shift == 0 && nval == 4) {
        uint4 v4 = __ldg(reinterpret_cast<const uint4*>(w) + (e0 >> 2));
        vals[0] = (int)v4.x; vals[1] = (int)v4.y;
        vals[2] = (int)v4.z; vals[3] = (int)v4.w;
    } else {
        #pragma unroll
        for (int k = 0; k < EDGES_PER_THREAD; ++k)
            if (k < nval)
                vals[k] = (int)__ldg(&w[((unsigned)(e0 + k)) << shift]);
    }

    int prev = (e0 == 0) ? -1 : (int)__ldg(&w[((unsigned)(e0 - 1)) << shift]);

    #pragma unroll
    for (int k = 0; k < EDGES_PER_THREAD; ++k) {
        if (k >= nval) break;
        int e = e0 + k;
        int cur = vals[k];
        for (int n = prev + 1; n <= cur; ++n)
            g_offsets[n] = e;
        if (e == E - 1) {
            for (int n = cur + 1; n <= N; ++n)
                g_offsets[n] = E;
        }
        prev = cur;
    }
}

// ---------------------------------------------------------------------------
// Kernel 2: ONE WARP PER SEGMENT — the winning R10/R12 loop shape (58.9us
// main, regs 44, DRAM 76.6%), now TEMPLATED on D so the D=128 instantiation
// has: no column loop, constant-immediate LDG offsets (base+512/1024/1536),
// and no runtime D multiplies. Unrolled x4 rows, 4 transient load regs, 2
// accumulators, then unroll-2 + scalar tails. (R11: manual predication
// serializes loads via BSSY -> 71us. R7: >2 live accumulators -> 72 regs ->
// 84us. Keep this shape.) Block=64. Lane l owns float4 column 4l. __ldcs
// read-once x stream, __stcs write-once output. Empty segments write zeros
// (output poisoned 0xAA, must be overwritten).
// ---------------------------------------------------------------------------
template <int DVAL>
__global__ void __launch_bounds__(BLOCK_THREADS)
segment_mean_kernel(const float* __restrict__ x,
                    float* __restrict__ out,
                    int Drt, int N) {
    const int D = (DVAL > 0) ? DVAL : Drt;
    int gwarp = (blockIdx.x * blockDim.x + threadIdx.x) >> 5;
    int lane  = threadIdx.x & 31;
    if (gwarp >= N) return;

    int s = __ldg(&g_offsets[gwarp]);
    int e = __ldg(&g_offsets[gwarp + 1]);
    int cnt = e - s;
    float inv = (cnt > 0) ? (1.0f / (float)cnt) : 0.0f;

    #pragma unroll 1
    for (int c = lane * 4; c < D; c += 32 * 4) {
        float4 a0 = make_float4(0.f, 0.f, 0.f, 0.f);
        float4 a1 = make_float4(0.f, 0.f, 0.f, 0.f);
        const float* p = x + (size_t)s * D + c;
        int r = s;
        for (; r + 4 <= e; r += 4, p += 4 * D) {
            float4 v0 = __ldcs(reinterpret_cast<const float4*>(p));
            float4 v1 = __ldcs(reinterpret_cast<const float4*>(p + D));
            float4 v2 = __ldcs(reinterpret_cast<const float4*>(p + 2 * D));
            float4 v3 = __ldcs(reinterpret_cast<const float4*>(p + 3 * D));
            a0.x += v0.x; a0.y += v0.y; a0.z += v0.z; a0.w += v0.w;
            a1.x += v1.x; a1.y += v1.y; a1.z += v1.z; a1.w += v1.w;
            a0.x += v2.x; a0.y += v2.y; a0.z += v2.z; a0.w += v2.w;
            a1.x += v3.x; a1.y += v3.y; a1.z += v3.z; a1.w += v3.w;
        }
        if (r + 2 <= e) {
            float4 v0 = __ldcs(reinterpret_cast<const float4*>(p));
            float4 v1 = __ldcs(reinterpret_cast<const float4*>(p + D));
            a0.x += v0.x; a0.y += v0.y; a0.z += v0.z; a0.w += v0.w;
            a1.x += v1.x; a1.y += v1.y; a1.z += v1.z; a1.w += v1.w;
            r += 2; p += 2 * D;
        }
        if (r < e) {
            float4 v0 = __ldcs(reinterpret_cast<const float4*>(p));
            a0.x += v0.x; a0.y += v0.y; a0.z += v0.z; a0.w += v0.w;
        }
        float4 res;
        res.x = (a0.x + a1.x) * inv;
        res.y = (a0.y + a1.y) * inv;
        res.z = (a0.z + a1.z) * inv;
        res.w = (a0.w + a1.w) * inv;
        __stcs(reinterpret_cast<float4*>(out + (size_t)gwarp * D + c), res);
    }
}

// ---------------------------------------------------------------------------
// Launch
// Inputs (metadata order): d_in[0] = x (float32, E*D), d_in[1] = index (E,
// int32 or int64 — detected on device), d_in[2] = dim_size (unused).
// ---------------------------------------------------------------------------
extern "C" void kernel_launch(void* const* d_in, const int* in_sizes, int n_in,
                              void* d_out, int out_size) {
    const float*        x   = (const float*)d_in[0];
    const unsigned int* idx = (const unsigned int*)d_in[1];
    float*              out = (float*)d_out;

    int E = in_sizes[1];          // 640000
    int D = in_sizes[0] / E;      // 128
    int N = out_size / D;         // 100000

    // Kernel 1: streaming segment boundaries, 4 edges per thread (uint4 path).
    {
        int threads = 256;
        long long work = ((long long)E + EDGES_PER_THREAD - 1) / EDGES_PER_THREAD;
        int blocks = (int)((work + threads - 1) / threads);
        build_offsets_kernel<<<blocks, threads>>>(idx, E, N);
    }

    // Kernel 2: one warp per segment, 2 warps per 64-thread block.
    {
        int warps_per_block = BLOCK_THREADS / 32;
        int blocks = (N + warps_per_block - 1) / warps_per_block;
        if (D == 128)
            segment_mean_kernel<128><<<blocks, BLOCK_THREADS>>>(x, out, D, N);
        else
            segment_mean_kernel<0><<<blocks, BLOCK_THREADS>>>(x, out, D, N);
    }
}